// round 2
// baseline (speedup 1.0000x reference)
#include <cuda_runtime.h>
#include <float.h>
#include <math.h>

// Problem constants
#define NPTS 12288
#define DIM 64
#define KNN 16
#define EPS 1e-5f
#define DIAG_BIAS 1e6f

// Tiling for the GEMM-style kNN kernel
#define NSEG 3
#define SEGJ (NPTS / NSEG)       // 4096 columns per CTA
#define BI 128                   // rows per CTA
#define BJ 64                    // cols per tile
#define NTILES (SEGJ / BJ)       // 64
#define THREADS 256
#define NROWBLK (NPTS / BI)      // 96

// k is processed in packed pairs
#define KSTEPS (DIM / 2)         // 32

// smem strides (floats), padded, multiples of 4 for LDS.128 alignment
#define SI_STRIDE (BI * 2 + 4)   // 260
#define SJ_STRIDE (BJ * 2 + 4)   // 132
#define SD_STRIDE (BJ + 4)       // 68

#define SI_OFF   0
#define SJ_OFF   (KSTEPS * SI_STRIDE)                 // 8320
#define SD_OFF   (SJ_OFF + KSTEPS * SJ_STRIDE)        // 12544
#define SSQI_OFF (SD_OFF + BI * SD_STRIDE)            // 21248
#define SSQJ_OFF (SSQI_OFF + BI)                      // 21376
#define SMEM_FLOATS (SSQJ_OFF + BJ)                   // 21440
#define SMEM_BYTES (SMEM_FLOATS * 4)                  // 85760

// Scratch (no allocations allowed -> device globals)
__device__ float g_sq[NPTS];
__device__ float g_colsum[DIM];
__device__ float g_sigma_inv;
__device__ float g_vals[NPTS * NSEG * KNN];
__device__ int   g_idx [NPTS * NSEG * KNN];

typedef unsigned long long u64;

__device__ __forceinline__ u64 ffma2(u64 a, u64 b, u64 c) {
    u64 d;
    asm("fma.rn.f32x2 %0, %1, %2, %3;" : "=l"(d) : "l"(a), "l"(b), "l"(c));
    return d;
}
__device__ __forceinline__ float pairsum(u64 a) {
    float lo = __uint_as_float((unsigned)(a & 0xffffffffull));
    float hi = __uint_as_float((unsigned)(a >> 32));
    return lo + hi;
}

// ---------------------------------------------------------------------------
// Kernel A1: per-row squared norm
// ---------------------------------------------------------------------------
__global__ void sq_kernel(const float* __restrict__ coords) {
    int row = blockIdx.x * 256 + threadIdx.x;
    const float4* p = (const float4*)(coords + (size_t)row * DIM);
    float s = 0.f;
#pragma unroll
    for (int t = 0; t < DIM / 4; ++t) {
        float4 v = p[t];
        s += v.x * v.x + v.y * v.y + v.z * v.z + v.w * v.w;
    }
    g_sq[row] = s;
}

// ---------------------------------------------------------------------------
// Kernel A1b: column sums (one block per dim)
// ---------------------------------------------------------------------------
__global__ void colsum_kernel(const float* __restrict__ coords) {
    __shared__ float red[256];
    int d = blockIdx.x;
    float s = 0.f;
    for (int r = threadIdx.x; r < NPTS; r += 256)
        s += coords[(size_t)r * DIM + d];
    red[threadIdx.x] = s;
    __syncthreads();
    for (int off = 128; off > 0; off >>= 1) {
        if (threadIdx.x < off) red[threadIdx.x] += red[threadIdx.x + off];
        __syncthreads();
    }
    if (threadIdx.x == 0) g_colsum[d] = red[0];
}

// ---------------------------------------------------------------------------
// Kernel A2: analytic sigma2
//   sum_ij dist2 = 2N*sum(sq) - 2*||colsum||^2 + N^2*EPS + N*DIAG_BIAS
// ---------------------------------------------------------------------------
__global__ void sigma_kernel() {
    __shared__ double red[256];
    double s = 0.0;
    for (int r = threadIdx.x; r < NPTS; r += 256)
        s += (double)g_sq[r];
    red[threadIdx.x] = s;
    __syncthreads();
    for (int off = 128; off > 0; off >>= 1) {
        if (threadIdx.x < off) red[threadIdx.x] += red[threadIdx.x + off];
        __syncthreads();
    }
    if (threadIdx.x == 0) {
        double sumsq = red[0];
        double nrm2 = 0.0;
        for (int d = 0; d < DIM; ++d) {
            double c = (double)g_colsum[d];
            nrm2 += c * c;
        }
        const double Nd = (double)NPTS;
        double total = 2.0 * Nd * sumsq - 2.0 * nrm2
                     + Nd * Nd * (double)EPS + Nd * (double)DIAG_BIAS;
        double sigma2 = total / (Nd * Nd);
        g_sigma_inv = (float)(1.0 / (sigma2 + (double)EPS));
    }
}

// ---------------------------------------------------------------------------
// Sorted insert: vals ascending, vals[KNN-1] is the threshold.
// ---------------------------------------------------------------------------
__device__ __forceinline__ void topk_insert(float (&vals)[KNN], int (&idx)[KNN],
                                            float v, int id) {
#pragma unroll
    for (int t = 0; t < KNN; ++t) {
        if (v < vals[t]) {
            float tv = vals[t]; vals[t] = v; v = tv;
            int   ti = idx[t];  idx[t]  = id; id = ti;
        }
    }
}

// ---------------------------------------------------------------------------
// Kernel B: GEMM-tiled distance + streaming top-16.
// CTA: 256 threads, 128 rows x (SEGJ) cols in 64-col tiles.
// Thread register tile: 8 rows x 4 cols, fp32x2-packed k accumulation.
// ---------------------------------------------------------------------------
__global__ void __launch_bounds__(THREADS, 1)
knn2_kernel(const float* __restrict__ coords) {
    extern __shared__ float smem[];
    float* si   = smem + SI_OFF;
    float* sj   = smem + SJ_OFF;
    float* sd   = smem + SD_OFF;
    float* ssqi = smem + SSQI_OFF;
    float* ssqj = smem + SSQJ_OFF;

    const int tid  = threadIdx.x;
    const int ty   = tid >> 4;     // 0..15 -> rows ty*8..ty*8+7
    const int tx   = tid & 15;     // 0..15 -> cols tx*4..tx*4+3
    const int row0 = blockIdx.x * BI;
    const int jseg = blockIdx.y * SEGJ;

    // ---- stage i-tile (128 rows x 64 dims), k-pair-major ----
    {
        const float4* src = (const float4*)(coords + (size_t)row0 * DIM);
#pragma unroll
        for (int u = 0; u < 8; ++u) {
            int idx = u * THREADS + tid;           // 0..2047
            int r = idx >> 4, kg = idx & 15;
            float4 v = src[idx];
            float2* d0 = (float2*)(si + (2 * kg + 0) * SI_STRIDE + r * 2);
            float2* d1 = (float2*)(si + (2 * kg + 1) * SI_STRIDE + r * 2);
            *d0 = make_float2(v.x, v.y);
            *d1 = make_float2(v.z, v.w);
        }
        if (tid < BI) ssqi[tid] = g_sq[row0 + tid];
    }

    // persistent top-k state (per thread: row = tid>>1, half = tid&1)
    const int trow = tid >> 1;
    const int thalf = tid & 1;
    float vals[KNN];
    int   idx[KNN];
#pragma unroll
    for (int t = 0; t < KNN; ++t) { vals[t] = FLT_MAX; idx[t] = 0; }

    for (int tile = 0; tile < NTILES; ++tile) {
        const int jbase = jseg + tile * BJ;
        __syncthreads();   // prev-tile dist reads done; i-tile ready (iter 0)

        // ---- stage j-tile (64 rows x 64 dims), k-pair-major ----
        {
            const float4* src = (const float4*)(coords + (size_t)jbase * DIM);
#pragma unroll
            for (int u = 0; u < 4; ++u) {
                int e = u * THREADS + tid;         // 0..1023
                int r = e >> 4, kg = e & 15;
                float4 v = src[e];
                float2* d0 = (float2*)(sj + (2 * kg + 0) * SJ_STRIDE + r * 2);
                float2* d1 = (float2*)(sj + (2 * kg + 1) * SJ_STRIDE + r * 2);
                *d0 = make_float2(v.x, v.y);
                *d1 = make_float2(v.z, v.w);
            }
            if (tid < BJ) ssqj[tid] = g_sq[jbase + tid];
        }
        __syncthreads();

        // ---- compute 8x4 register tile, packed fp32x2 over k ----
        u64 acc[8][4];
#pragma unroll
        for (int r = 0; r < 8; ++r)
#pragma unroll
            for (int c = 0; c < 4; ++c) acc[r][c] = 0ull;

        const float* sib = si + ty * 16;
        const float* sjb = sj + tx * 8;
#pragma unroll 4
        for (int s = 0; s < KSTEPS; ++s) {
            u64 ai[8], bj[4];
            {
                const ulonglong2* p = (const ulonglong2*)(sib + s * SI_STRIDE);
                ulonglong2 v0 = p[0], v1 = p[1], v2 = p[2], v3 = p[3];
                ai[0] = v0.x; ai[1] = v0.y; ai[2] = v1.x; ai[3] = v1.y;
                ai[4] = v2.x; ai[5] = v2.y; ai[6] = v3.x; ai[7] = v3.y;
            }
            {
                const ulonglong2* p = (const ulonglong2*)(sjb + s * SJ_STRIDE);
                ulonglong2 v0 = p[0], v1 = p[1];
                bj[0] = v0.x; bj[1] = v0.y; bj[2] = v1.x; bj[3] = v1.y;
            }
#pragma unroll
            for (int r = 0; r < 8; ++r)
#pragma unroll
                for (int c = 0; c < 4; ++c)
                    acc[r][c] = ffma2(ai[r], bj[c], acc[r][c]);
        }

        // ---- assemble distances, write dist tile to smem ----
        {
            float sqj4[4];
#pragma unroll
            for (int c = 0; c < 4; ++c) sqj4[c] = ssqj[tx * 4 + c];
#pragma unroll
            for (int r = 0; r < 8; ++r) {
                const int lr = ty * 8 + r;
                const int gr = row0 + lr;
                const float base = ssqi[lr] + EPS;
                float4 dv;
                float* dd = (float*)&dv;
#pragma unroll
                for (int c = 0; c < 4; ++c) {
                    float dot = pairsum(acc[r][c]);
                    float d = fmaf(-2.f, dot, base + sqj4[c]);
                    if (gr == jbase + tx * 4 + c) d += DIAG_BIAS;
                    dd[c] = d;
                }
                *(float4*)(sd + lr * SD_STRIDE + tx * 4) = dv;
            }
        }
        __syncthreads();

        // ---- streaming top-16: 2 threads per row, 32 cols each ----
        {
            const float* rp = sd + trow * SD_STRIDE + thalf * 32;
            const int cbase = jbase + thalf * 32;
#pragma unroll
            for (int c4 = 0; c4 < 8; ++c4) {
                float4 d = *(const float4*)(rp + c4 * 4);
                const int cb = cbase + c4 * 4;
                if (d.x < vals[KNN - 1]) topk_insert(vals, idx, d.x, cb + 0);
                if (d.y < vals[KNN - 1]) topk_insert(vals, idx, d.y, cb + 1);
                if (d.z < vals[KNN - 1]) topk_insert(vals, idx, d.z, cb + 2);
                if (d.w < vals[KNN - 1]) topk_insert(vals, idx, d.w, cb + 3);
            }
        }
    }

    // ---- merge the two half-row lists, emit per-segment candidates ----
    __syncthreads();
    float* svals = sd;                       // reuse dist buffer
    int*   sidx  = (int*)(sd + BI * KNN);
    if (thalf == 1) {
#pragma unroll
        for (int t = 0; t < KNN; ++t) {
            svals[trow * KNN + t] = vals[t];
            sidx [trow * KNN + t] = idx[t];
        }
    }
    __syncthreads();
    if (thalf == 0) {
#pragma unroll
        for (int t = 0; t < KNN; ++t) {
            float c = svals[trow * KNN + t];
            if (c < vals[KNN - 1]) topk_insert(vals, idx, c, sidx[trow * KNN + t]);
        }
        const size_t o = ((size_t)(row0 + trow) * NSEG + blockIdx.y) * KNN;
#pragma unroll
        for (int t = 0; t < KNN; ++t) {
            g_vals[o + t] = vals[t];
            g_idx [o + t] = idx[t];
        }
    }
}

// ---------------------------------------------------------------------------
// Kernel C: merge NSEG candidate lists per row, compute Laplacian.
// ---------------------------------------------------------------------------
__global__ void merge_lap_kernel(const float* __restrict__ potential,
                                 float* __restrict__ out) {
    const int row = blockIdx.x * 256 + threadIdx.x;

    float vals[KNN];
    int   idx[KNN];
#pragma unroll
    for (int t = 0; t < KNN; ++t) { vals[t] = FLT_MAX; idx[t] = 0; }

    const size_t base = (size_t)row * NSEG * KNN;
    for (int s = 0; s < NSEG; ++s) {
#pragma unroll
        for (int kk = 0; kk < KNN; ++kk) {
            float c = g_vals[base + s * KNN + kk];
            if (c < vals[KNN - 1]) topk_insert(vals, idx, c, g_idx[base + s * KNN + kk]);
        }
    }

    const float inv = g_sigma_inv;
    const float vi  = potential[row];
    float lap = 0.f;
#pragma unroll
    for (int t = 0; t < KNN; ++t) {
        float w = expf(-vals[t] * inv);
        lap += w * (potential[idx[t]] - vi);
    }
    out[row] = lap;
}

// ---------------------------------------------------------------------------
extern "C" void kernel_launch(void* const* d_in, const int* in_sizes, int n_in,
                              void* d_out, int out_size) {
    const float* coords    = (const float*)d_in[0];
    const float* potential = (const float*)d_in[1];
    float* out = (float*)d_out;

    static bool attr_set = false;
    if (!attr_set) {
        cudaFuncSetAttribute(knn2_kernel,
                             cudaFuncAttributeMaxDynamicSharedMemorySize,
                             SMEM_BYTES);
        attr_set = true;
    }

    sq_kernel<<<NPTS / 256, 256>>>(coords);
    colsum_kernel<<<DIM, 256>>>(coords);
    sigma_kernel<<<1, 256>>>();

    dim3 grid(NROWBLK, NSEG);
    knn2_kernel<<<grid, THREADS, SMEM_BYTES>>>(coords);

    merge_lap_kernel<<<NPTS / 256, 256>>>(potential, out);
}